// round 11
// baseline (speedup 1.0000x reference)
#include <cuda_runtime.h>
#include <cuda_fp16.h>
#include <cstdint>
#include <math.h>

typedef unsigned long long ull;

#define HEADS   8
#define DHQK    32
#define DHV     32
#define BSZ     8
#define HALO    3
#define WIN     14
#define WIN2    196
#define QKVW    768
#define NPIX    4096
#define NBATCH  16
#define SCALE_QK 0.17677669529663687f

// Scratch: fused qkv per pixel, layout [b][pix][768]:
//   [0,256)   q  : channel = head*32 + d
//   [256,768) kv : channel = head*64 + d (k: d<32, v: d>=32)
__device__ float g_qkv[(size_t)NBATCH * NPIX * QKVW];

// ---------- packed f32x2 helpers ----------
__device__ __forceinline__ ull pk2(float lo, float hi) {
    ull r; asm("mov.b64 %0, {%1, %2};" : "=l"(r) : "f"(lo), "f"(hi)); return r;
}
__device__ __forceinline__ ull fma2(ull a, ull b, ull c) {
    ull d; asm("fma.rn.f32x2 %0, %1, %2, %3;" : "=l"(d) : "l"(a), "l"(b), "l"(c)); return d;
}
__device__ __forceinline__ float2 upk2(ull v) {
    float2 r; asm("mov.b64 {%0, %1}, %2;" : "=f"(r.x), "=f"(r.y) : "l"(v)); return r;
}

// =====================================================================
// Kernel 1: fused QKV projection GEMM (f32x2), double-buffered,
//   conflict-free B fragments (thread n-tile 4+4).  [~430us, 88% of f32x2 peak]
// =====================================================================
__global__ __launch_bounds__(256) void qkv_gemm(const float* __restrict__ x,
                                                const float* __restrict__ Wq,
                                                const float* __restrict__ Wkv) {
    __shared__ float As[2][16 * 128];   // [buf][kk][m]
    __shared__ float Bs[2][16 * 132];   // [buf][kk][n] stride 132

    const int n0   = blockIdx.x * 128;
    const int mblk = blockIdx.y;
    const int b    = mblk >> 5;
    const int pix0 = (mblk & 31) << 7;

    const float* xb = x + ((size_t)b * 256) * NPIX + pix0;
    const float* Wb = (n0 < 256) ? (Wq + (size_t)n0 * 256)
                                 : (Wkv + (size_t)(n0 - 256) * 256);

    const int tid = threadIdx.x;
    const int tmg = tid >> 4;
    const int tng = tid & 15;

    const int la_c  = tid >> 5;
    const int la_m4 = (tid & 31) << 2;
    const int lb_o  = tid >> 1;
    const int lb_k8 = (tid & 1) << 3;

    ull acc[8][4];
    #pragma unroll
    for (int i = 0; i < 8; ++i)
        #pragma unroll
        for (int j = 0; j < 4; ++j) acc[i][j] = 0ull;

    #pragma unroll
    for (int i = 0; i < 2; ++i) {
        int c = la_c + i * 8;
        *(float4*)(&As[0][c * 128 + la_m4]) =
            *(const float4*)(xb + (size_t)c * NPIX + la_m4);
    }
    #pragma unroll
    for (int i = 0; i < 2; ++i) {
        float4 wv = *(const float4*)(Wb + (size_t)lb_o * 256 + lb_k8 + i * 4);
        Bs[0][(lb_k8 + i * 4 + 0) * 132 + lb_o] = wv.x;
        Bs[0][(lb_k8 + i * 4 + 1) * 132 + lb_o] = wv.y;
        Bs[0][(lb_k8 + i * 4 + 2) * 132 + lb_o] = wv.z;
        Bs[0][(lb_k8 + i * 4 + 3) * 132 + lb_o] = wv.w;
    }
    __syncthreads();

    for (int c = 0; c < 16; ++c) {
        const int cur = c & 1, nxt = cur ^ 1;

        float4 a_reg[2], b_reg[2];
        if (c < 15) {
            const int kc = (c + 1) * 16;
            #pragma unroll
            for (int i = 0; i < 2; ++i)
                a_reg[i] = *(const float4*)(xb + (size_t)(kc + la_c + i * 8) * NPIX + la_m4);
            #pragma unroll
            for (int i = 0; i < 2; ++i)
                b_reg[i] = *(const float4*)(Wb + (size_t)lb_o * 256 + kc + lb_k8 + i * 4);
        }

        #pragma unroll
        for (int kk = 0; kk < 16; ++kk) {
            float4 a0 = *(const float4*)(&As[cur][kk * 128 + tmg * 8]);
            float4 a1 = *(const float4*)(&As[cur][kk * 128 + tmg * 8 + 4]);
            float4 b0 = *(const float4*)(&Bs[cur][kk * 132 + tng * 4]);
            float4 b1 = *(const float4*)(&Bs[cur][kk * 132 + 64 + tng * 4]);
            ull bp0 = pk2(b0.x, b0.y), bp1 = pk2(b0.z, b0.w);
            ull bp2 = pk2(b1.x, b1.y), bp3 = pk2(b1.z, b1.w);
            float av[8] = {a0.x, a0.y, a0.z, a0.w, a1.x, a1.y, a1.z, a1.w};
            #pragma unroll
            for (int i = 0; i < 8; ++i) {
                ull ad = pk2(av[i], av[i]);
                acc[i][0] = fma2(ad, bp0, acc[i][0]);
                acc[i][1] = fma2(ad, bp1, acc[i][1]);
                acc[i][2] = fma2(ad, bp2, acc[i][2]);
                acc[i][3] = fma2(ad, bp3, acc[i][3]);
            }
        }

        if (c < 15) {
            #pragma unroll
            for (int i = 0; i < 2; ++i)
                *(float4*)(&As[nxt][(la_c + i * 8) * 128 + la_m4]) = a_reg[i];
            #pragma unroll
            for (int i = 0; i < 2; ++i) {
                Bs[nxt][(lb_k8 + i * 4 + 0) * 132 + lb_o] = b_reg[i].x;
                Bs[nxt][(lb_k8 + i * 4 + 1) * 132 + lb_o] = b_reg[i].y;
                Bs[nxt][(lb_k8 + i * 4 + 2) * 132 + lb_o] = b_reg[i].z;
                Bs[nxt][(lb_k8 + i * 4 + 3) * 132 + lb_o] = b_reg[i].w;
            }
        }
        __syncthreads();
    }

    const size_t mbase = (size_t)b * NPIX + pix0;
    #pragma unroll
    for (int i = 0; i < 8; ++i) {
        int m = tmg * 8 + i;
        float2 p0 = upk2(acc[i][0]), p1 = upk2(acc[i][1]);
        float2 p2 = upk2(acc[i][2]), p3 = upk2(acc[i][3]);
        float* op = g_qkv + (mbase + m) * QKVW + n0 + tng * 4;
        *(float4*)(op)      = make_float4(p0.x, p0.y, p1.x, p1.y);
        *(float4*)(op + 64) = make_float4(p2.x, p2.y, p3.x, p3.y);
    }
}

// =====================================================================
// Kernel 2: halo block attention — R6 skeleton (single barrier, fp32 P,
//   2 CTAs/SM) with lane-distinct fp16 compression of K and V:
//     Qt [32 d][68]  f32   (broadcast LDS.128 pairs in QK)
//     Kh [16 d2][197] u32 = half2(K[2d2][k], K[2d2+1][k])  (lane-consec reads)
//     Vh [98 k2][36]  u32 = half2(V[2k2][d], V[2k2+1][d])  (lane-consec reads)
//     Ps [64 r][200]  f32  (broadcast LDS.128 in PV, no cvt)
// =====================================================================
#define QT_ST 68
#define KH_ST 197
#define VH_ST 36
#define P_ST  200
#define QT_FL (32 * QT_ST)                    // 2176 floats
#define KH_U  (16 * KH_ST)                    // 3152 u32
#define VH_U  (98 * VH_ST)                    // 3528 u32
#define AT_SMEM_FLOATS (QT_FL + KH_U + VH_U + 64 * P_ST)
#define AT_SMEM_BYTES  (AT_SMEM_FLOATS * 4)   // 86,624

__global__ __launch_bounds__(256, 2) void attn_kernel(const float* __restrict__ pos_bias,
                                                      float* __restrict__ out) {
    extern __shared__ float sm[];
    float*    Qt = sm;                               // [32][68] f32
    uint32_t* Kh = (uint32_t*)(sm + QT_FL);          // [16][197] half2 d-pairs
    uint32_t* Vh = Kh + KH_U;                        // [98][36]  half2 k-pairs
    float*    Ps = sm + QT_FL + KH_U + VH_U;         // [64][200] f32

    const int nb = blockIdx.x, h = blockIdx.y, b = blockIdx.z;
    const int by = nb >> 3, bx = nb & 7;
    const int tid = threadIdx.x;
    const int w = tid >> 5, lane = tid & 31;
    const int w8 = w * 8;
    const float* qkv_b = g_qkv + (size_t)b * NPIX * QKVW;

    // ---- gather: K -> half2 d-pairs, 1568 (pixel, d-quad) items ----
    for (int idx = tid; idx < WIN2 * 8; idx += 256) {
        const int kk = idx >> 3, d4 = (idx & 7) << 2;
        const int wy = kk / WIN, wx = kk - wy * WIN;
        const int py = by * BSZ - HALO + wy, px = bx * BSZ - HALO + wx;
        const bool ok = ((unsigned)py < 64u) && ((unsigned)px < 64u);
        const float4 z4 = make_float4(0.f, 0.f, 0.f, 0.f);
        float4 kv = ok ? *(const float4*)(qkv_b + (py * 64 + px) * QKVW + 256 + h * 64 + d4)
                       : z4;
        __half2 h0 = __floats2half2_rn(kv.x, kv.y);   // (K[d4],   K[d4+1])
        __half2 h1 = __floats2half2_rn(kv.z, kv.w);   // (K[d4+2], K[d4+3])
        Kh[((d4 >> 1) + 0) * KH_ST + kk] = *(uint32_t*)&h0;
        Kh[((d4 >> 1) + 1) * KH_ST + kk] = *(uint32_t*)&h1;
    }
    // ---- gather: V -> half2 k-pairs, 784 (k2, d-quad) items ----
    for (int idx = tid; idx < 98 * 8; idx += 256) {
        const int k2 = idx >> 3, d4 = (idx & 7) << 2;
        const int k0 = 2 * k2, k1 = k0 + 1;
        const int wy0 = k0 / WIN, wx0 = k0 - wy0 * WIN;
        const int wy1 = k1 / WIN, wx1 = k1 - wy1 * WIN;
        const int py0 = by * BSZ - HALO + wy0, px0 = bx * BSZ - HALO + wx0;
        const int py1 = by * BSZ - HALO + wy1, px1 = bx * BSZ - HALO + wx1;
        const float4 z4 = make_float4(0.f, 0.f, 0.f, 0.f);
        float4 a = (((unsigned)py0 < 64u) && ((unsigned)px0 < 64u))
            ? *(const float4*)(qkv_b + (py0 * 64 + px0) * QKVW + 256 + h * 64 + 32 + d4) : z4;
        float4 c = (((unsigned)py1 < 64u) && ((unsigned)px1 < 64u))
            ? *(const float4*)(qkv_b + (py1 * 64 + px1) * QKVW + 256 + h * 64 + 32 + d4) : z4;
        __half2 h0 = __floats2half2_rn(a.x, c.x);
        __half2 h1 = __floats2half2_rn(a.y, c.y);
        __half2 h2 = __floats2half2_rn(a.z, c.z);
        __half2 h3 = __floats2half2_rn(a.w, c.w);
        uint4 st;
        st.x = *(uint32_t*)&h0; st.y = *(uint32_t*)&h1;
        st.z = *(uint32_t*)&h2; st.w = *(uint32_t*)&h3;
        *(uint4*)(&Vh[k2 * VH_ST + d4]) = st;
    }
    // ---- gather: Q fp32 (r = idx&63 so STS banks span rows) ----
    #pragma unroll
    for (int it = 0; it < 2; ++it) {
        const int idx = tid + it * 256;
        const int q4 = (idx >> 6) << 2, r = idx & 63;
        const int py = by * BSZ + (r >> 3), px = bx * BSZ + (r & 7);
        float4 qv = *(const float4*)(qkv_b + (py * 64 + px) * QKVW + h * DHQK + q4);
        Qt[(q4 + 0) * QT_ST + r] = qv.x;
        Qt[(q4 + 1) * QT_ST + r] = qv.y;
        Qt[(q4 + 2) * QT_ST + r] = qv.z;
        Qt[(q4 + 3) * QT_ST + r] = qv.w;
    }
    __syncthreads();      // the only CTA barrier

    // ---- QK: rows-packed f32x2; K via lane-distinct half2 d-pairs ----
    ull s2[4][7];
    #pragma unroll
    for (int j = 0; j < 4; ++j)
        #pragma unroll
        for (int nc = 0; nc < 7; ++nc) s2[j][nc] = 0ull;

    #pragma unroll 2
    for (int d2 = 0; d2 < 16; ++d2) {
        // one u32 per chunk yields K for BOTH d = 2*d2 and 2*d2+1
        ull ka[7], kb[7];
        #pragma unroll
        for (int nc = 0; nc < 7; ++nc) {
            uint32_t u = Kh[d2 * KH_ST + nc * 32 + lane];
            float2 kf = __half22float2(*(__half2*)&u);
            ka[nc] = pk2(kf.x, kf.x);
            kb[nc] = pk2(kf.y, kf.y);
        }
        const int d0 = 2 * d2;
        float4 qa0 = *(const float4*)(Qt + d0 * QT_ST + w8);
        float4 qb0 = *(const float4*)(Qt + d0 * QT_ST + w8 + 4);
        float4 qa1 = *(const float4*)(Qt + (d0 + 1) * QT_ST + w8);
        float4 qb1 = *(const float4*)(Qt + (d0 + 1) * QT_ST + w8 + 4);
        ull p01a = pk2(qa0.x, qa0.y), p23a = pk2(qa0.z, qa0.w);
        ull p45a = pk2(qb0.x, qb0.y), p67a = pk2(qb0.z, qb0.w);
        ull p01b = pk2(qa1.x, qa1.y), p23b = pk2(qa1.z, qa1.w);
        ull p45b = pk2(qb1.x, qb1.y), p67b = pk2(qb1.z, qb1.w);
        #pragma unroll
        for (int nc = 0; nc < 7; ++nc) {
            s2[0][nc] = fma2(p01a, ka[nc], s2[0][nc]);
            s2[1][nc] = fma2(p23a, ka[nc], s2[1][nc]);
            s2[2][nc] = fma2(p45a, ka[nc], s2[2][nc]);
            s2[3][nc] = fma2(p67a, ka[nc], s2[3][nc]);
            s2[0][nc] = fma2(p01b, kb[nc], s2[0][nc]);
            s2[1][nc] = fma2(p23b, kb[nc], s2[1][nc]);
            s2[2][nc] = fma2(p45b, kb[nc], s2[2][nc]);
            s2[3][nc] = fma2(p67b, kb[nc], s2[3][nc]);
        }
    }

    // ---- bias + mask + softmax (unnormalized fp32 P; inv kept in regs) ----
    const float* pbase = pos_bias + (size_t)(h * 64 + w8) * WIN2;
    const float NEG = -1e30f;
    float inv_[8];
    #pragma unroll
    for (int j = 0; j < 4; ++j) {
        #pragma unroll
        for (int rr = 0; rr < 2; ++rr) {
            const int mi = 2 * j + rr;
            float s[7];
            #pragma unroll
            for (int nc = 0; nc < 7; ++nc) {
                float2 t = upk2(s2[j][nc]);
                float sv = rr ? t.y : t.x;
                int kk = nc * 32 + lane;
                s[nc] = (kk < WIN2) ? fmaf(sv, SCALE_QK, pbase[mi * WIN2 + kk]) : NEG;
            }
            float mx = s[0];
            #pragma unroll
            for (int nc = 1; nc < 7; ++nc) mx = fmaxf(mx, s[nc]);
            #pragma unroll
            for (int off = 16; off > 0; off >>= 1)
                mx = fmaxf(mx, __shfl_xor_sync(0xffffffffu, mx, off));
            float sum = 0.f;
            #pragma unroll
            for (int nc = 0; nc < 7; ++nc) {
                float e = __expf(s[nc] - mx);
                s[nc] = e;
                sum += e;
            }
            #pragma unroll
            for (int off = 16; off > 0; off >>= 1)
                sum += __shfl_xor_sync(0xffffffffu, sum, off);
            inv_[mi] = 1.f / sum;
            float* prow = Ps + (w8 + mi) * P_ST;
            #pragma unroll
            for (int nc = 0; nc < 6; ++nc)
                prow[nc * 32 + lane] = s[nc];
            if (lane < 4) prow[192 + lane] = s[6];
        }
    }
    __syncwarp();   // warp-private P rows visible across the warp

    // ---- PV: V lane-distinct half2 k-pairs; P broadcast LDS.128 fp32 ----
    ull acc2[8];
    #pragma unroll
    for (int mi = 0; mi < 8; ++mi) acc2[mi] = 0ull;
    const float* prow = Ps + w8 * P_ST;
    #pragma unroll 2
    for (int k4 = 0; k4 < 49; ++k4) {
        uint32_t u0 = Vh[(2 * k4 + 0) * VH_ST + lane];
        uint32_t u1 = Vh[(2 * k4 + 1) * VH_ST + lane];
        float2 f0 = __half22float2(*(__half2*)&u0);   // (V[4k4],   V[4k4+1])
        float2 f1 = __half22float2(*(__half2*)&u1);   // (V[4k4+2], V[4k4+3])
        ull vA = pk2(f0.x, f0.y), vB = pk2(f1.x, f1.y);
        #pragma unroll
        for (int mi = 0; mi < 8; ++mi) {
            float4 p = *(const float4*)(prow + mi * P_ST + 4 * k4);   // bcast
            acc2[mi] = fma2(pk2(p.x, p.y), vA, acc2[mi]);
            acc2[mi] = fma2(pk2(p.z, p.w), vB, acc2[mi]);
        }
    }

    // ---- epilogue: lane d writes out[d][by*8+w][bx*8 .. +7] directly ----
    float o[8];
    #pragma unroll
    for (int mi = 0; mi < 8; ++mi) {
        float2 t = upk2(acc2[mi]);
        o[mi] = (t.x + t.y) * inv_[mi];
    }
    float* op = out + (((size_t)(b * HEADS + h) * DHV + lane) * 64 + by * BSZ + w) * 64
                    + bx * BSZ;
    *(float4*)(op)     = make_float4(o[0], o[1], o[2], o[3]);
    *(float4*)(op + 4) = make_float4(o[4], o[5], o[6], o[7]);
}

// =====================================================================
extern "C" void kernel_launch(void* const* d_in, const int* in_sizes, int n_in,
                              void* d_out, int out_size) {
    const float* x   = (const float*)d_in[0];
    const float* Wq  = (const float*)d_in[1];
    const float* Wkv = (const float*)d_in[2];
    const float* pb  = (const float*)d_in[3];
    float* out = (float*)d_out;

    // 1) fused QKV projection (f32x2, double-buffered, conflict-free B)
    qkv_gemm<<<dim3(6, 512), 256>>>(x, Wq, Wkv);

    // 2) halo attention (R6 skeleton + lane-distinct fp16 K and V)
    cudaFuncSetAttribute(attn_kernel,
                         cudaFuncAttributeMaxDynamicSharedMemorySize, AT_SMEM_BYTES);
    attn_kernel<<<dim3(64, HEADS, NBATCH), 256, AT_SMEM_BYTES>>>(pb, out);
}

// round 12
// speedup vs baseline: 1.0155x; 1.0155x over previous
#include <cuda_runtime.h>
#include <cuda_fp16.h>
#include <cstdint>
#include <math.h>

typedef unsigned long long ull;

#define HEADS   8
#define DHQK    32
#define DHV     32
#define BSZ     8
#define HALO    3
#define WIN     14
#define WIN2    196
#define QKVW    768
#define NPIX    4096
#define NBATCH  16
#define SCALE_QK 0.17677669529663687f

// Scratch: fused qkv per pixel, layout [b][pix][768]:
//   [0,256)   q  : channel = head*32 + d
//   [256,768) kv : channel = head*64 + d (k: d<32, v: d>=32)
__device__ float g_qkv[(size_t)NBATCH * NPIX * QKVW];

// ---------- packed f32x2 helpers ----------
__device__ __forceinline__ ull pk2(float lo, float hi) {
    ull r; asm("mov.b64 %0, {%1, %2};" : "=l"(r) : "f"(lo), "f"(hi)); return r;
}
__device__ __forceinline__ ull fma2(ull a, ull b, ull c) {
    ull d; asm("fma.rn.f32x2 %0, %1, %2, %3;" : "=l"(d) : "l"(a), "l"(b), "l"(c)); return d;
}
__device__ __forceinline__ float2 upk2(ull v) {
    float2 r; asm("mov.b64 {%0, %1}, %2;" : "=f"(r.x), "=f"(r.y) : "l"(v)); return r;
}

// =====================================================================
// Kernel 1: fused QKV projection GEMM (f32x2), double-buffered,
//   conflict-free B fragments (thread n-tile 4+4).  [R6: ~430us]
// =====================================================================
__global__ __launch_bounds__(256) void qkv_gemm(const float* __restrict__ x,
                                                const float* __restrict__ Wq,
                                                const float* __restrict__ Wkv) {
    __shared__ float As[2][16 * 128];   // [buf][kk][m]
    __shared__ float Bs[2][16 * 132];   // [buf][kk][n] stride 132

    const int n0   = blockIdx.x * 128;
    const int mblk = blockIdx.y;
    const int b    = mblk >> 5;
    const int pix0 = (mblk & 31) << 7;

    const float* xb = x + ((size_t)b * 256) * NPIX + pix0;
    const float* Wb = (n0 < 256) ? (Wq + (size_t)n0 * 256)
                                 : (Wkv + (size_t)(n0 - 256) * 256);

    const int tid = threadIdx.x;
    const int tmg = tid >> 4;
    const int tng = tid & 15;

    const int la_c  = tid >> 5;
    const int la_m4 = (tid & 31) << 2;
    const int lb_o  = tid >> 1;
    const int lb_k8 = (tid & 1) << 3;

    ull acc[8][4];
    #pragma unroll
    for (int i = 0; i < 8; ++i)
        #pragma unroll
        for (int j = 0; j < 4; ++j) acc[i][j] = 0ull;

    #pragma unroll
    for (int i = 0; i < 2; ++i) {
        int c = la_c + i * 8;
        *(float4*)(&As[0][c * 128 + la_m4]) =
            *(const float4*)(xb + (size_t)c * NPIX + la_m4);
    }
    #pragma unroll
    for (int i = 0; i < 2; ++i) {
        float4 wv = *(const float4*)(Wb + (size_t)lb_o * 256 + lb_k8 + i * 4);
        Bs[0][(lb_k8 + i * 4 + 0) * 132 + lb_o] = wv.x;
        Bs[0][(lb_k8 + i * 4 + 1) * 132 + lb_o] = wv.y;
        Bs[0][(lb_k8 + i * 4 + 2) * 132 + lb_o] = wv.z;
        Bs[0][(lb_k8 + i * 4 + 3) * 132 + lb_o] = wv.w;
    }
    __syncthreads();

    for (int c = 0; c < 16; ++c) {
        const int cur = c & 1, nxt = cur ^ 1;

        float4 a_reg[2], b_reg[2];
        if (c < 15) {
            const int kc = (c + 1) * 16;
            #pragma unroll
            for (int i = 0; i < 2; ++i)
                a_reg[i] = *(const float4*)(xb + (size_t)(kc + la_c + i * 8) * NPIX + la_m4);
            #pragma unroll
            for (int i = 0; i < 2; ++i)
                b_reg[i] = *(const float4*)(Wb + (size_t)lb_o * 256 + kc + lb_k8 + i * 4);
        }

        #pragma unroll
        for (int kk = 0; kk < 16; ++kk) {
            float4 a0 = *(const float4*)(&As[cur][kk * 128 + tmg * 8]);
            float4 a1 = *(const float4*)(&As[cur][kk * 128 + tmg * 8 + 4]);
            float4 b0 = *(const float4*)(&Bs[cur][kk * 132 + tng * 4]);
            float4 b1 = *(const float4*)(&Bs[cur][kk * 132 + 64 + tng * 4]);
            ull bp0 = pk2(b0.x, b0.y), bp1 = pk2(b0.z, b0.w);
            ull bp2 = pk2(b1.x, b1.y), bp3 = pk2(b1.z, b1.w);
            float av[8] = {a0.x, a0.y, a0.z, a0.w, a1.x, a1.y, a1.z, a1.w};
            #pragma unroll
            for (int i = 0; i < 8; ++i) {
                ull ad = pk2(av[i], av[i]);
                acc[i][0] = fma2(ad, bp0, acc[i][0]);
                acc[i][1] = fma2(ad, bp1, acc[i][1]);
                acc[i][2] = fma2(ad, bp2, acc[i][2]);
                acc[i][3] = fma2(ad, bp3, acc[i][3]);
            }
        }

        if (c < 15) {
            #pragma unroll
            for (int i = 0; i < 2; ++i)
                *(float4*)(&As[nxt][(la_c + i * 8) * 128 + la_m4]) = a_reg[i];
            #pragma unroll
            for (int i = 0; i < 2; ++i) {
                Bs[nxt][(lb_k8 + i * 4 + 0) * 132 + lb_o] = b_reg[i].x;
                Bs[nxt][(lb_k8 + i * 4 + 1) * 132 + lb_o] = b_reg[i].y;
                Bs[nxt][(lb_k8 + i * 4 + 2) * 132 + lb_o] = b_reg[i].z;
                Bs[nxt][(lb_k8 + i * 4 + 3) * 132 + lb_o] = b_reg[i].w;
            }
        }
        __syncthreads();
    }

    const size_t mbase = (size_t)b * NPIX + pix0;
    #pragma unroll
    for (int i = 0; i < 8; ++i) {
        int m = tmg * 8 + i;
        float2 p0 = upk2(acc[i][0]), p1 = upk2(acc[i][1]);
        float2 p2 = upk2(acc[i][2]), p3 = upk2(acc[i][3]);
        float* op = g_qkv + (mbase + m) * QKVW + n0 + tng * 4;
        *(float4*)(op)      = make_float4(p0.x, p0.y, p1.x, p1.y);
        *(float4*)(op + 64) = make_float4(p2.x, p2.y, p3.x, p3.y);
    }
}

// =====================================================================
// Kernel 2: halo block attention — R6 verbatim EXCEPT V is half2
//   k-pair packed (lane-distinct cvt at head of PV iteration):
//     Qt [32 d][68]  f32   (broadcast LDS.128 pairs in QK)
//     Kt [32 d][197] f32   (lane-consecutive scalar reads)
//     Vh [98 k2][36] u32 = half2(V[2k2][d], V[2k2+1][d])
//     Ps [64 r][196] f32   (broadcast LDS.128 in PV, no cvt)
//   Single CTA barrier after gather; direct STG.128 epilogue.
// =====================================================================
#define QT_ST 68
#define KT_ST 197
#define VH_ST 36
#define QT_FL (32 * QT_ST)                    // 2176 floats
#define KT_FL (32 * KT_ST)                    // 6304 floats
#define VH_U  (98 * VH_ST)                    // 3528 u32
#define AT_SMEM_FLOATS (QT_FL + KT_FL + VH_U + 64 * WIN2)
#define AT_SMEM_BYTES  (AT_SMEM_FLOATS * 4)   // 98,208

__global__ __launch_bounds__(256, 2) void attn_kernel(const float* __restrict__ pos_bias,
                                                      float* __restrict__ out) {
    extern __shared__ float sm[];
    float*    Qt = sm;                           // [32][68]
    float*    Kt = sm + QT_FL;                   // [32][197]
    uint32_t* Vh = (uint32_t*)(sm + QT_FL + KT_FL);  // [98][36]
    float*    Ps = sm + QT_FL + KT_FL + VH_U;    // [64][196]

    const int nb = blockIdx.x, h = blockIdx.y, b = blockIdx.z;
    const int by = nb >> 3, bx = nb & 7;
    const int tid = threadIdx.x;
    const int w = tid >> 5, lane = tid & 31;
    const int w8 = w * 8;
    const float* qkv_b = g_qkv + (size_t)b * NPIX * QKVW;

    // ---- gather: K fp32, 1568 (pixel, d-quad) items ----
    for (int idx = tid; idx < WIN2 * 8; idx += 256) {
        const int kk = idx >> 3, d4 = (idx & 7) << 2;
        const int wy = kk / WIN, wx = kk - wy * WIN;
        const int py = by * BSZ - HALO + wy, px = bx * BSZ - HALO + wx;
        const bool ok = ((unsigned)py < 64u) && ((unsigned)px < 64u);
        const float4 z4 = make_float4(0.f, 0.f, 0.f, 0.f);
        float4 kv = ok ? *(const float4*)(qkv_b + (py * 64 + px) * QKVW + 256 + h * 64 + d4)
                       : z4;
        Kt[(d4 + 0) * KT_ST + kk] = kv.x;
        Kt[(d4 + 1) * KT_ST + kk] = kv.y;
        Kt[(d4 + 2) * KT_ST + kk] = kv.z;
        Kt[(d4 + 3) * KT_ST + kk] = kv.w;
    }
    // ---- gather: V -> half2 k-pairs, 784 (k2, d-quad) items ----
    for (int idx = tid; idx < 98 * 8; idx += 256) {
        const int k2 = idx >> 3, d4 = (idx & 7) << 2;
        const int k0 = 2 * k2, k1 = k0 + 1;
        const int wy0 = k0 / WIN, wx0 = k0 - wy0 * WIN;
        const int wy1 = k1 / WIN, wx1 = k1 - wy1 * WIN;
        const int py0 = by * BSZ - HALO + wy0, px0 = bx * BSZ - HALO + wx0;
        const int py1 = by * BSZ - HALO + wy1, px1 = bx * BSZ - HALO + wx1;
        const float4 z4 = make_float4(0.f, 0.f, 0.f, 0.f);
        float4 a = (((unsigned)py0 < 64u) && ((unsigned)px0 < 64u))
            ? *(const float4*)(qkv_b + (py0 * 64 + px0) * QKVW + 256 + h * 64 + 32 + d4) : z4;
        float4 c = (((unsigned)py1 < 64u) && ((unsigned)px1 < 64u))
            ? *(const float4*)(qkv_b + (py1 * 64 + px1) * QKVW + 256 + h * 64 + 32 + d4) : z4;
        __half2 h0 = __floats2half2_rn(a.x, c.x);
        __half2 h1 = __floats2half2_rn(a.y, c.y);
        __half2 h2 = __floats2half2_rn(a.z, c.z);
        __half2 h3 = __floats2half2_rn(a.w, c.w);
        uint4 st;
        st.x = *(uint32_t*)&h0; st.y = *(uint32_t*)&h1;
        st.z = *(uint32_t*)&h2; st.w = *(uint32_t*)&h3;
        *(uint4*)(&Vh[k2 * VH_ST + d4]) = st;
    }
    // ---- gather: Q fp32 (r = idx&63 so STS banks span rows) ----
    #pragma unroll
    for (int it = 0; it < 2; ++it) {
        const int idx = tid + it * 256;
        const int q4 = (idx >> 6) << 2, r = idx & 63;
        const int py = by * BSZ + (r >> 3), px = bx * BSZ + (r & 7);
        float4 qv = *(const float4*)(qkv_b + (py * 64 + px) * QKVW + h * DHQK + q4);
        Qt[(q4 + 0) * QT_ST + r] = qv.x;
        Qt[(q4 + 1) * QT_ST + r] = qv.y;
        Qt[(q4 + 2) * QT_ST + r] = qv.z;
        Qt[(q4 + 3) * QT_ST + r] = qv.w;
    }
    __syncthreads();      // the only CTA barrier

    // ---- QK: rows-packed f32x2, K fp32 lane-consecutive (R6 verbatim) ----
    ull s2[4][7];
    #pragma unroll
    for (int j = 0; j < 4; ++j)
        #pragma unroll
        for (int nc = 0; nc < 7; ++nc) s2[j][nc] = 0ull;

    #pragma unroll 4
    for (int d = 0; d < 32; ++d) {
        ull kv2[7];
        #pragma unroll
        for (int nc = 0; nc < 7; ++nc) {
            float kf = Kt[d * KT_ST + nc * 32 + lane];
            kv2[nc] = pk2(kf, kf);
        }
        float4 qa = *(const float4*)(Qt + d * QT_ST + w8);       // rows 0-3 (bcast)
        float4 qb = *(const float4*)(Qt + d * QT_ST + w8 + 4);   // rows 4-7
        ull q01 = pk2(qa.x, qa.y), q23 = pk2(qa.z, qa.w);
        ull q45 = pk2(qb.x, qb.y), q67 = pk2(qb.z, qb.w);
        #pragma unroll
        for (int nc = 0; nc < 7; ++nc) {
            s2[0][nc] = fma2(q01, kv2[nc], s2[0][nc]);
            s2[1][nc] = fma2(q23, kv2[nc], s2[1][nc]);
            s2[2][nc] = fma2(q45, kv2[nc], s2[2][nc]);
            s2[3][nc] = fma2(q67, kv2[nc], s2[3][nc]);
        }
    }

    // ---- bias + mask + softmax (unnormalized fp32 P; inv kept in regs) ----
    const float* pbase = pos_bias + (size_t)(h * 64 + w8) * WIN2;
    const float NEG = -1e30f;
    float inv_[8];
    #pragma unroll
    for (int j = 0; j < 4; ++j) {
        #pragma unroll
        for (int rr = 0; rr < 2; ++rr) {
            const int mi = 2 * j + rr;
            float s[7];
            #pragma unroll
            for (int nc = 0; nc < 7; ++nc) {
                float2 t = upk2(s2[j][nc]);
                float sv = rr ? t.y : t.x;
                int kk = nc * 32 + lane;
                s[nc] = (kk < WIN2) ? fmaf(sv, SCALE_QK, pbase[mi * WIN2 + kk]) : NEG;
            }
            float mx = s[0];
            #pragma unroll
            for (int nc = 1; nc < 7; ++nc) mx = fmaxf(mx, s[nc]);
            #pragma unroll
            for (int off = 16; off > 0; off >>= 1)
                mx = fmaxf(mx, __shfl_xor_sync(0xffffffffu, mx, off));
            float sum = 0.f;
            #pragma unroll
            for (int nc = 0; nc < 7; ++nc) {
                float e = __expf(s[nc] - mx);
                s[nc] = e;
                sum += e;
            }
            #pragma unroll
            for (int off = 16; off > 0; off >>= 1)
                sum += __shfl_xor_sync(0xffffffffu, sum, off);
            inv_[mi] = 1.f / sum;
            float* prow = Ps + (w8 + mi) * WIN2;
            #pragma unroll
            for (int nc = 0; nc < 6; ++nc)
                prow[nc * 32 + lane] = s[nc];
            if (lane < 4) prow[192 + lane] = s[6];
        }
    }
    __syncwarp();   // warp-private P rows visible across the warp

    // ---- PV: V lane-distinct half2 k-pairs; P broadcast LDS.128 fp32 ----
    ull acc2[8];
    #pragma unroll
    for (int mi = 0; mi < 8; ++mi) acc2[mi] = 0ull;
    const float* prow = Ps + w8 * WIN2;
    #pragma unroll 2
    for (int k4 = 0; k4 < 49; ++k4) {
        uint32_t u0 = Vh[(2 * k4 + 0) * VH_ST + lane];
        uint32_t u1 = Vh[(2 * k4 + 1) * VH_ST + lane];
        float2 f0 = __half22float2(*(__half2*)&u0);   // (V[4k4],   V[4k4+1])
        float2 f1 = __half22float2(*(__half2*)&u1);   // (V[4k4+2], V[4k4+3])
        ull vA = pk2(f0.x, f0.y), vB = pk2(f1.x, f1.y);
        #pragma unroll
        for (int mi = 0; mi < 8; ++mi) {
            float4 p = *(const float4*)(prow + mi * WIN2 + 4 * k4);   // bcast
            acc2[mi] = fma2(pk2(p.x, p.y), vA, acc2[mi]);
            acc2[mi] = fma2(pk2(p.z, p.w), vB, acc2[mi]);
        }
    }

    // ---- epilogue: lane d writes out[d][by*8+w][bx*8 .. +7] directly ----
    float o[8];
    #pragma unroll
    for (int mi = 0; mi < 8; ++mi) {
        float2 t = upk2(acc2[mi]);
        o[mi] = (t.x + t.y) * inv_[mi];
    }
    float* op = out + (((size_t)(b * HEADS + h) * DHV + lane) * 64 + by * BSZ + w) * 64
                    + bx * BSZ;
    *(float4*)(op)     = make_float4(o[0], o[1], o[2], o[3]);
    *(float4*)(op + 4) = make_float4(o[4], o[5], o[6], o[7]);
}

// =====================================================================
extern "C" void kernel_launch(void* const* d_in, const int* in_sizes, int n_in,
                              void* d_out, int out_size) {
    const float* x   = (const float*)d_in[0];
    const float* Wq  = (const float*)d_in[1];
    const float* Wkv = (const float*)d_in[2];
    const float* pb  = (const float*)d_in[3];
    float* out = (float*)d_out;

    // 1) fused QKV projection (f32x2, double-buffered, conflict-free B)
    qkv_gemm<<<dim3(6, 512), 256>>>(x, Wq, Wkv);

    // 2) halo attention (R6 + V fp16 k-pairs ONLY)
    cudaFuncSetAttribute(attn_kernel,
                         cudaFuncAttributeMaxDynamicSharedMemorySize, AT_SMEM_BYTES);
    attn_kernel<<<dim3(64, HEADS, NBATCH), 256, AT_SMEM_BYTES>>>(pb, out);
}